// round 17
// baseline (speedup 1.0000x reference)
#include <cuda_runtime.h>
#include <cuda_fp16.h>
#include <cstdint>
#include <cstddef>

// ============================================================================
// LSTM fused persistent kernel (R16 resubmit — audit found no defect;
// prior two "container failed twice" results were infra flakes that passed
// on verbatim resubmission).
// conv_x: x -> fp16, relaid t-major: g_x16[(t*32+b)][d].
// ONE persistent kernel, 128 CTAs x 384 threads:
//   warps 0-3 (low wid = low arbiter priority): xproj producer. Per chunk t,
//     computes the CTA's own (32 b x 32 gate-col) tile x_t @ Wx-slice + bias
//     and writes it to a 2-stage SMEM ring (no global round-trip).
//   warps 4-11 (high wid): recurrence, split-N (warp = m16n8, no cross-warp
//     reduce), shfl epilogue, per-CTA dataflow flags across CTAs.
// ============================================================================

#define DI __device__ __forceinline__

DI uint32_t smem_u32(const void* p) { return (uint32_t)__cvta_generic_to_shared(p); }

DI void cp16cg(const void* smem_dst, const void* gsrc) {
    asm volatile("cp.async.cg.shared.global [%0], [%1], 16;"
                 :: "r"(smem_u32(smem_dst)), "l"(gsrc));
}
DI void cp_commit() { asm volatile("cp.async.commit_group;"); }
template<int N> DI void cp_wait() { asm volatile("cp.async.wait_group %0;" :: "n"(N)); }

DI unsigned ld_acq_gpu(const unsigned* p) {
    unsigned v;
    asm volatile("ld.acquire.gpu.u32 %0, [%1];" : "=r"(v) : "l"(p));
    return v;
}
DI void st_rel_gpu(unsigned* p, unsigned v) {
    asm volatile("st.release.gpu.u32 [%0], %1;" :: "l"(p), "r"(v) : "memory");
}
DI void bar_sync(int id, int cnt) {
    asm volatile("bar.sync %0, %1;" :: "r"(id), "r"(cnt) : "memory");
}
DI int lds_vol_s32(uint32_t addr) {
    int v;
    asm volatile("ld.volatile.shared.s32 %0, [%1];" : "=r"(v) : "r"(addr));
    return v;
}
DI void sts_vol_s32(uint32_t addr, int v) {
    asm volatile("st.volatile.shared.s32 [%0], %1;" :: "r"(addr), "r"(v) : "memory");
}
DI void lds_vol_v4f(float* v, uint32_t addr) {
    asm volatile("ld.volatile.shared.v4.f32 {%0,%1,%2,%3}, [%4];"
                 : "=f"(v[0]), "=f"(v[1]), "=f"(v[2]), "=f"(v[3]) : "r"(addr));
}
DI void sts_v2f(uint32_t addr, float a, float b) {
    asm volatile("st.shared.v2.f32 [%0], {%1,%2};" :: "r"(addr), "f"(a), "f"(b) : "memory");
}

DI void mma_f16(float* c, const uint32_t* a, const uint32_t* b) {
    asm volatile(
        "mma.sync.aligned.m16n8k16.row.col.f32.f16.f16.f32 "
        "{%0,%1,%2,%3}, {%4,%5,%6,%7}, {%8,%9}, {%0,%1,%2,%3};"
        : "+f"(c[0]), "+f"(c[1]), "+f"(c[2]), "+f"(c[3])
        : "r"(a[0]), "r"(a[1]), "r"(a[2]), "r"(a[3]), "r"(b[0]), "r"(b[1]));
}

DI void ldsm4(uint32_t* r, uint32_t addr) {
    asm volatile("ldmatrix.sync.aligned.m8n8.x4.shared.b16 {%0,%1,%2,%3}, [%4];"
                 : "=r"(r[0]), "=r"(r[1]), "=r"(r[2]), "=r"(r[3]) : "r"(addr));
}

DI float fast_sigmoid(float x) { return 1.f / (1.f + __expf(-x)); }
DI float fast_tanh(float x) {
    float e = __expf(-2.f * x);
    return (1.f - e) / (1.f + e);
}

// Scratch (allocation-free rule: __device__ globals)
__device__ __half g_x16[16384 * 1024];       // 32 MB: fp16 X, rows t*32+b
__device__ __half g_hh[2][32][1024];         // fp16 h, ping-pong by t parity
__device__ unsigned g_flags[128 * 32];       // per-CTA completed-step counters

// ----------------------------------------------------------------------------
// conv_x: X (b,t,d) fp32 -> g_x16 row (t*32+b) fp16
// ----------------------------------------------------------------------------
__global__ void conv_x(const float* __restrict__ X) {
    size_t i8 = ((size_t)blockIdx.x * 256 + threadIdx.x) * 8;
    float4 a = *(const float4*)(X + i8);
    float4 b = *(const float4*)(X + i8 + 4);
    __half2 h[4];
    h[0] = __floats2half2_rn(a.x, a.y);
    h[1] = __floats2half2_rn(a.z, a.w);
    h[2] = __floats2half2_rn(b.x, b.y);
    h[3] = __floats2half2_rn(b.z, b.w);
    int row = (int)(i8 >> 10);
    int d = (int)(i8 & 1023);
    int bb = row >> 9, tt = row & 511;
    *(uint4*)(g_x16 + ((size_t)(tt * 32 + bb) << 10) + d) = *(const uint4*)h;
}

// ----------------------------------------------------------------------------
// init: clear flags; seed g_hh[0] = fp16(h0)
// ----------------------------------------------------------------------------
__global__ void init_kernel(const float* __restrict__ h0) {
    int i = blockIdx.x * 256 + threadIdx.x;
    if (i < 128 * 32) g_flags[i] = 0u;
    for (int idx = i; idx < 32 * 1024; idx += 4096)
        g_hh[0][idx >> 10][idx & 1023] = __float2half(h0[idx]);
}

// ----------------------------------------------------------------------------
// Fused persistent kernel.
// SMEM layout (224896 B total):
//   [0)        sWhT  fp16 Wh^T [32 cc][1032 k]         66048
//   [66048)    sWxT  fp16 Wx^T [32 cc][1032 k]         66048
//   [132096)   sHh   fp16 h    [32 b][1032 k]          66048
//   [198144)   xA    fp16 2 bufs x 32 rows x 136       17408
//   [215552)   xP    f32  2 stages x 32 b x 36 cc      9216
//   [224768)   ctrl: xprog (int), xcons (int)          128
// Gate-col ordering (j-major): cc = j*4 + q, physical col = q*1024 + c8 + j.
// ----------------------------------------------------------------------------
static const int ROW_HALVES = 1032;
static const int WT_BYTES   = 32 * ROW_HALVES * 2;      // 66048
static const int SWHT_OFF   = 0;
static const int SWXT_OFF   = WT_BYTES;
static const int SHH_OFF    = 2 * WT_BYTES;             // 132096
static const int XA_OFF     = 3 * WT_BYTES;             // 198144
static const int XA_STRIDE  = 136;
static const int XA_BYTES   = 32 * XA_STRIDE * 2;       // 8704
static const int XP_OFF     = XA_OFF + 2 * XA_BYTES;    // 215552
static const int XP_STAGE_B = 32 * 36 * 4;              // 4608
static const int CTRL_OFF   = XP_OFF + 2 * XP_STAGE_B;  // 224768
static const int SMEM_BYTES = CTRL_OFF + 128;           // 224896

__global__ void __launch_bounds__(384, 1) lstm_fused(
    const float* __restrict__ Wh, const float* __restrict__ Wx,
    const float* __restrict__ bias, float* __restrict__ out)
{
    extern __shared__ __align__(16) char dyn[];
    __half (*sWhT)[ROW_HALVES] = reinterpret_cast<__half (*)[ROW_HALVES]>(dyn + SWHT_OFF);
    __half (*sWxT)[ROW_HALVES] = reinterpret_cast<__half (*)[ROW_HALVES]>(dyn + SWXT_OFF);
    __half (*sHh)[ROW_HALVES]  = reinterpret_cast<__half (*)[ROW_HALVES]>(dyn + SHH_OFF);

    const uint32_t sb       = smem_u32(dyn);
    const uint32_t xprog_a  = sb + CTRL_OFF;
    const uint32_t xcons_a  = sb + CTRL_OFF + 4;
    const uint32_t xp_base  = sb + XP_OFF;

    const int tid = threadIdx.x;
    const int warp = tid >> 5, lane = tid & 31;
    const int cta = blockIdx.x;
    const int c8  = cta * 8;

    // ---- One-time init: resident W tiles (j-major cc = j*4+q) ----
    for (int idx = tid; idx < 32 * 1024; idx += 384) {
        int k = idx >> 5, cc = idx & 31;
        int q = cc & 3, j = cc >> 2;
        size_t gcol = (size_t)k * 4096 + q * 1024 + c8 + j;
        sWhT[cc][k] = __float2half(Wh[gcol]);
        sWxT[cc][k] = __float2half(Wx[gcol]);
    }
    if (tid == 0) { sts_vol_s32(xprog_a, 0); sts_vol_s32(xcons_a, 0); }
    __syncthreads();

    const int gid = lane >> 2, tig = lane & 3;
    // LDSM lane offsets (A pattern validated R14; B 8-row pattern verified
    // against the PTX m16n8k16 fragment spec)
    const int arow = lane & 15;
    const int acol = (lane >> 4) * 8;
    const int brow = lane & 7;
    const int bcol = 8 * (lane >> 3);

    if (warp < 4) {
        // ================= xproj producer (warps 0-3, low priority) ==========
        __half (*xA)[XA_STRIDE] = reinterpret_cast<__half (*)[XA_STRIDE]>(dyn + XA_OFF);
        const int xw = warp;                   // n8 block: cc in [8xw, 8xw+8)
        const int cc0 = xw * 8 + 2 * tig;
        const float b0 = bias[(cc0 & 3) * 1024 + c8 + (cc0 >> 2)];
        const float b1 = bias[((cc0 + 1) & 3) * 1024 + c8 + ((cc0 + 1) >> 2)];

        auto stage = [&](int buf, int tch, int kc) {
            // 32 rows x 128 halves piece = 512 x 16B; 128 threads x 4 slices
#pragma unroll
            for (int c = 0; c < 4; ++c) {
                int slice = tid * 4 + c;               // 0..511
                int r = slice >> 4, s = slice & 15;
                cp16cg(&xA[buf * 32 + r][s * 8],
                       g_x16 + ((size_t)(tch * 32 + r) << 10) + kc * 128 + s * 8);
            }
            cp_commit();
        };

        for (int tch = 0; tch < 512; ++tch) {
            stage(0, tch, 0);
            float acc[2][2][4];
#pragma unroll
            for (int m = 0; m < 2; ++m)
#pragma unroll
                for (int p = 0; p < 2; ++p)
#pragma unroll
                    for (int r = 0; r < 4; ++r) acc[m][p][r] = 0.f;

            for (int kc = 0; kc < 8; ++kc) {
                const int buf = kc & 1;
                if (kc < 7) { stage(buf ^ 1, tch, kc + 1); cp_wait<1>(); }
                else cp_wait<0>();
                bar_sync(2, 128);
#pragma unroll
                for (int blk = 0; blk < 4; ++blk) {
                    const int kg = kc * 128 + blk * 32;
                    uint32_t b4[4];
                    ldsm4(b4, smem_u32(&sWxT[xw * 8 + brow][kg + bcol]));
#pragma unroll
                    for (int sub = 0; sub < 2; ++sub) {
                        uint32_t af[2][4];
#pragma unroll
                        for (int m = 0; m < 2; ++m)
                            ldsm4(af[m], smem_u32(&xA[buf * 32 + m * 16 + arow]
                                                     [blk * 32 + sub * 16 + acol]));
#pragma unroll
                        for (int m = 0; m < 2; ++m)
                            mma_f16(acc[m][blk & 1], af[m], &b4[sub * 2]);
                    }
                }
                bar_sync(2, 128);   // reads of xA[buf] done before next refill
            }

            // Ring backpressure: stage tch%2 reusable only after consumer
            // finished step tch-2 (xcons >= tch-1).
            if (tch >= 2) { while (lds_vol_s32(xcons_a) < tch - 1) { } }

            // Write 32x32 tile (+bias) into xP[tch&1]
            const uint32_t st_base = xp_base + (uint32_t)(tch & 1) * XP_STAGE_B;
#pragma unroll
            for (int m = 0; m < 2; ++m) {
#pragma unroll
                for (int rr = 0; rr < 2; ++rr) {
                    int b = m * 16 + gid + 8 * rr;
                    float v0 = acc[m][0][rr * 2] + acc[m][1][rr * 2] + b0;
                    float v1 = acc[m][0][rr * 2 + 1] + acc[m][1][rr * 2 + 1] + b1;
                    sts_v2f(st_base + (uint32_t)b * 144 + cc0 * 4, v0, v1);
                }
            }
            bar_sync(2, 128);       // bar drains STS -> tile visible
            if (tid == 0) sts_vol_s32(xprog_a, tch + 1);
        }
    } else {
        // ================= recurrence (warps 4-11, high priority) ============
        const int rw = warp - 4;               // 0..7
        const int mb = rw >> 2, nb = rw & 3;   // m16 block, n8 block
        const int tidr = tid - 128;            // 0..255
        const int mycol8 = (tidr & 127) * 8;
        const int rowoff = tidr >> 7;
        const unsigned* myfl = &g_flags[(tidr & 127) * 32];

        const int b_cell = mb * 16 + gid + 8 * (tig & 1);
        const int j_cell = 2 * nb + (tig >> 1);
        const bool even = (tig & 1) == 0;
        const uint32_t xp_addr0 = xp_base + (uint32_t)b_cell * 144 + (uint32_t)j_cell * 16;

        float creg = 0.f;

        for (int t = 0; t < 512; ++t) {
            // Own-CTA xproj tile ready?
            while (lds_vol_s32(xprog_a) < t + 1) { }
            float xp[4];
            lds_vol_v4f(xp, xp_addr0 + (uint32_t)(t & 1) * XP_STAGE_B);

            const __half* hp = &g_hh[t & 1][0][0];
            if (t > 0) { while (ld_acq_gpu(myfl) < (unsigned)t) { } }
#pragma unroll
            for (int k = 0; k < 16; ++k) {
                int r = 2 * k + rowoff;
                cp16cg(&sHh[r][mycol8], hp + ((size_t)r << 10) + mycol8);
            }
            cp_commit();
            cp_wait<0>();
            bar_sync(1, 256);          // full h staged

            // split-N mma: warp tile m16 x n8 over k=1024
            float a4[4][4];
#pragma unroll
            for (int p = 0; p < 4; ++p)
#pragma unroll
                for (int r = 0; r < 4; ++r) a4[p][r] = 0.f;

#pragma unroll
            for (int blk = 0; blk < 32; ++blk) {
                const int kg = blk * 32;
                uint32_t b4[4];
                ldsm4(b4, smem_u32(&sWhT[nb * 8 + brow][kg + bcol]));
#pragma unroll
                for (int sub = 0; sub < 2; ++sub) {
                    uint32_t af[4];
                    ldsm4(af, smem_u32(&sHh[mb * 16 + arow][kg + sub * 16 + acol]));
                    mma_f16(a4[blk & 3], af, &b4[sub * 2]);
                }
            }
            float c0 = a4[0][0] + a4[1][0] + a4[2][0] + a4[3][0];
            float c1 = a4[0][1] + a4[1][1] + a4[2][1] + a4[3][1];
            float c2 = a4[0][2] + a4[1][2] + a4[2][2] + a4[3][2];
            float c3 = a4[0][3] + a4[1][3] + a4[2][3] + a4[3][3];

            // shfl epilogue: lane^1 partner carries the other gate pair
            float o0 = __shfl_xor_sync(0xFFFFFFFFu, c0, 1);
            float o1 = __shfl_xor_sync(0xFFFFFFFFu, c1, 1);
            float o2 = __shfl_xor_sync(0xFFFFFFFFu, c2, 1);
            float o3 = __shfl_xor_sync(0xFFFFFFFFu, c3, 1);
            float iv = even ? c0 : o2;
            float fv = even ? c1 : o3;
            float ov = even ? o0 : c2;
            float gv = even ? o1 : c3;

            float ig = fast_sigmoid(iv + xp[0]);
            float fg = fast_sigmoid(fv + xp[1]);
            float og = fast_sigmoid(ov + xp[2]);
            float gg = fast_tanh(gv + xp[3]);
            creg = fg * creg + ig * gg;
            float hval = og * fast_tanh(creg);
            g_hh[(t + 1) & 1][b_cell][c8 + j_cell] = __float2half(hval);
            out[((size_t)b_cell * 512 + t) * 1024 + c8 + j_cell] = hval;

            bar_sync(1, 256);          // stores done + xP reads done
            if (tidr == 0) {
                st_rel_gpu(&g_flags[cta * 32], (unsigned)(t + 1));
                sts_vol_s32(xcons_a, t + 1);
            }
        }
    }
}

// ----------------------------------------------------------------------------
extern "C" void kernel_launch(void* const* d_in, const int* in_sizes, int n_in,
                              void* d_out, int out_size)
{
    const float* x  = (const float*)d_in[0];   // (32,512,1024)
    const float* h0 = (const float*)d_in[1];   // (32,1024)
    const float* Wx = (const float*)d_in[2];   // (1024,4096)
    const float* Wh = (const float*)d_in[3];   // (1024,4096)
    const float* b  = (const float*)d_in[4];   // (4096,)
    float* out = (float*)d_out;                // (32,512,1024)

    cudaFuncSetAttribute(lstm_fused,
                         cudaFuncAttributeMaxDynamicSharedMemorySize, SMEM_BYTES);

    conv_x<<<8192, 256>>>(x);
    init_kernel<<<16, 256>>>(h0);
    lstm_fused<<<128, 384, SMEM_BYTES>>>(Wh, Wx, b, out);
}